// round 6
// baseline (speedup 1.0000x reference)
#include <cuda_runtime.h>

#define B_      2048
#define D_      512
#define NA_     512
#define CAP_    32
#define NVMAX_  8
#define WARPS_  8
#define RPW_    64                    // rows per warp (512 / 8 warps)
#define TILES_  8                     // 8-row tiles per warp
#define PITCH4_ 68                    // float4 pitch per tile row (64 + 4 pad)
#define CHUNK4_ (8 * PITCH4_)         // float4 per 8row x 256k chunk = 544
#define TILE4_  (WARPS_ * CHUNK4_)    // 4352 float4
#define SMEMB_  ((TILE4_ + NVMAX_ * 128) * 16)   // 86016 bytes dynamic

// ---------------- device scratch ----------------
__device__ int g_counts[NA_];
__device__ int g_buckets[NA_ * CAP_];
__device__ int g_ovf_count;
__device__ int g_ovf[B_];

// ---------------- kernel 1: zero + bucket (single block) ----------------
__global__ void k_prep(const int* __restrict__ attrs) {
    int tid = threadIdx.x;                 // 1024 threads
    if (tid < NA_) g_counts[tid] = 0;
    if (tid == NA_) g_ovf_count = 0;
    __syncthreads();
    for (int b = tid; b < B_; b += 1024) {
        int a = attrs[b];
        int pos = atomicAdd(&g_counts[a], 1);
        if (pos < CAP_) {
            g_buckets[a * CAP_ + pos] = b;
        } else {
            int o = atomicAdd(&g_ovf_count, 1);
            g_ovf[o] = b;
        }
    }
}

// ---------------- per-warp pass: 64 rows x 512 k x NV samples ------------
// lane = (row 0..7, k-class 0..3). Matrix staged 8rows x 256k per chunk into
// pitched smem (conflict-free both sides); 16 LDG.128 (8KB) always in flight.
// Per 16-k iter: 1 matrix LDS.128 shared across all NV samples; v = 64B bcast.
template <int NV>
__device__ __forceinline__ void run_pass(
    const float* __restrict__ M,
    float4* __restrict__ smem4,        // dynamic smem base
    const int* __restrict__ ssamp,
    int nv, float* __restrict__ out, int warp, int lane)
{
    float4* buf = smem4 + warp * CHUNK4_;
    const float4* sv4 = smem4 + TILE4_;
    const float4* g = (const float4*)M;

    int r0base = warp * RPW_;
    int row_r  = lane >> 2;            // reader row within tile
    int c_r    = lane & 3;             // reader k-class

    // prefetch chunk (tile 0, half 0)
    float4 pf[16];
#pragma unroll
    for (int i = 0; i < 16; i++)
        pf[i] = g[(size_t)(r0base + (i >> 1)) * 128 + (i & 1) * 32 + lane];

#pragma unroll 1
    for (int t = 0; t < TILES_; t++) {
        float acc[NV];
#pragma unroll
        for (int j = 0; j < NV; j++) acc[j] = 0.0f;

#pragma unroll 1
        for (int h = 0; h < 2; h++) {
            __syncwarp();              // prior compute done before overwrite
#pragma unroll
            for (int i = 0; i < 16; i++)
                buf[(i >> 1) * PITCH4_ + (i & 1) * 32 + lane] = pf[i];

            // prefetch next chunk (stays in flight through compute)
            int nt = t, nh = h + 1;
            if (nh == 2) { nh = 0; nt = t + 1; }
            if (nt < TILES_) {
#pragma unroll
                for (int i = 0; i < 16; i++)
                    pf[i] = g[(size_t)(r0base + nt * 8 + (i >> 1)) * 128
                              + nh * 64 + (i & 1) * 32 + lane];
            }
            __syncwarp();              // STS visible to all lanes

#pragma unroll 4
            for (int i = 0; i < 16; i++) {
                float4 m = buf[row_r * PITCH4_ + i * 4 + c_r];
#pragma unroll
                for (int j = 0; j < NV; j++) {
                    float4 v = sv4[j * 128 + h * 64 + i * 4 + c_r];
                    acc[j] = fmaf(m.x, v.x, acc[j]);
                    acc[j] = fmaf(m.y, v.y, acc[j]);
                    acc[j] = fmaf(m.z, v.z, acc[j]);
                    acc[j] = fmaf(m.w, v.w, acc[j]);
                }
            }
        }

        // quad-reduce (2 shfl) and store: 8 lanes write 8 consecutive rows
        int row = r0base + t * 8 + row_r;
#pragma unroll
        for (int j = 0; j < NV; j++) {
            float x = acc[j];
            x += __shfl_xor_sync(0xffffffffu, x, 1);
            x += __shfl_xor_sync(0xffffffffu, x, 2);
            if (j < nv && c_r == 0)
                out[(size_t)ssamp[j] * D_ + row] = (x > 0.0f) ? x : 0.0f;
        }
    }
}

// ---------------- kernel 2: per-attribute matvec ------------------------
// grid = NA_ CTAs, 256 threads (8 warps), 86KB dynamic smem.
__global__ __launch_bounds__(256) void k_compute(
    const int*   __restrict__ attrs,
    const int*   __restrict__ objs,
    const float* __restrict__ attr_ops,
    const float* __restrict__ obj_emb,
    float*       __restrict__ out)
{
    extern __shared__ float4 smem4[];
    __shared__ int ssamp[NVMAX_];
    float4* sv4 = smem4 + TILE4_;

    int tid  = threadIdx.x;
    int lane = tid & 31;
    int warp = tid >> 5;
    int a    = blockIdx.x;

    int cnt = g_counts[a];
    if (cnt > CAP_) cnt = CAP_;
    const float* M = attr_ops + (size_t)a * D_ * D_;

    for (int base = 0; base < cnt; base += NVMAX_) {
        int nv = cnt - base;
        if (nv > NVMAX_) nv = NVMAX_;
        int NVsel = (nv <= 1) ? 1 : (nv <= 2) ? 2 : (nv <= 4) ? 4 : 8;

        __syncthreads();               // protect ssamp/sv reuse
        if (tid < nv) ssamp[tid] = g_buckets[a * CAP_ + base + tid];
        __syncthreads();

        // load vectors (zero-pad up to NVsel)
        for (int u = tid; u < NVsel * 128; u += 256) {
            int j = u >> 7;
            float4 val = make_float4(0.f, 0.f, 0.f, 0.f);
            if (j < nv) {
                int o = objs[ssamp[j]];
                val = ((const float4*)(obj_emb + (size_t)o * D_))[u & 127];
            }
            sv4[u] = val;
        }
        __syncthreads();

        switch (NVsel) {
            case 1: run_pass<1>(M, smem4, ssamp, nv, out, warp, lane); break;
            case 2: run_pass<2>(M, smem4, ssamp, nv, out, warp, lane); break;
            case 4: run_pass<4>(M, smem4, ssamp, nv, out, warp, lane); break;
            default: run_pass<8>(M, smem4, ssamp, nv, out, warp, lane); break;
        }
    }

    // ---- overflow tail (rare; correctness safety net) ----
    int novf = g_ovf_count;
    for (int i = blockIdx.x; i < novf; i += gridDim.x) {
        __syncthreads();
        if (tid == 0) ssamp[0] = g_ovf[i];
        __syncthreads();
        int b = ssamp[0];
        int o = objs[b];
        for (int u = tid; u < 128; u += 256)
            sv4[u] = ((const float4*)(obj_emb + (size_t)o * D_))[u];
        __syncthreads();
        run_pass<1>(attr_ops + (size_t)attrs[b] * D_ * D_,
                    smem4, ssamp, 1, out, warp, lane);
    }
}

// ---------------- launch -------------------------------------------------
extern "C" void kernel_launch(void* const* d_in, const int* in_sizes, int n_in,
                              void* d_out, int out_size)
{
    const int*   attrs    = (const int*)d_in[0];
    const int*   objs     = (const int*)d_in[1];
    const float* attr_ops = (const float*)d_in[2];
    const float* obj_emb  = (const float*)d_in[3];
    float*       out      = (float*)d_out;

    cudaFuncSetAttribute(k_compute,
                         cudaFuncAttributeMaxDynamicSharedMemorySize, SMEMB_);

    k_prep<<<1, 1024>>>(attrs);
    k_compute<<<NA_, 256, SMEMB_>>>(attrs, objs, attr_ops, obj_emb, out);
}